// round 2
// baseline (speedup 1.0000x reference)
#include <cuda_runtime.h>
#include <math.h>
#include <float.h>

#define NB    32
#define MROWS 100000
#define WC    64
#define RR    9
#define NIF   138
#define DIN   512
#define NBLK  40          // scan blocks per batch
#define CHUNK 2500        // rows per scan block (NBLK*CHUNK == MROWS)
#define NCAND (NBLK*8)    // 320 candidates per batch

// -------- scratch (no allocation allowed) --------
__device__ float g_q[NB][WC];            // read_query
__device__ float g_rows[NB][RR][WC];     // updated memory rows at rp
__device__ float g_cand_d[NB][NCAND];
__device__ int   g_cand_i[NB][NCAND];

__device__ __forceinline__ bool lt_pair(float d1, int i1, float d2, int i2) {
    return d1 < d2 || (d1 == d2 && i1 < i2);
}

// ================= Kernel 1: iface + derived small state =================
__global__ void k_iface(const float* __restrict__ xi, const float* __restrict__ Wm,
                        const float* __restrict__ b_lin, const float* __restrict__ usage,
                        const float* __restrict__ read_w, const float* __restrict__ rvec,
                        const int* __restrict__ rpos) {
    int b = blockIdx.x;
    __shared__ float sx[DIN];
    __shared__ float sif[NIF];
    __shared__ float sww[RR];
    __shared__ float swv[WC];

    for (int i = threadIdx.x; i < DIN; i += blockDim.x) sx[i] = xi[b * DIN + i];
    __syncthreads();

    int j = threadIdx.x;
    if (j < NIF) {
        float acc = b_lin[j];
        #pragma unroll 8
        for (int d = 0; d < DIN; d++) acc = fmaf(sx[d], Wm[d * NIF + j], acc);
        sif[j] = acc;
        if (j < WC) g_q[b][j] = acc;           // read_query
        if (j >= WC && j < 2 * WC) swv[j - WC] = acc;  // write_vector
    }
    __syncthreads();

    if (threadIdx.x == 0) {
        float wg = 1.f / (1.f + expf(-sif[NIF - 1]));
        float rel[RR];
        float minu = INFINITY;
        #pragma unroll
        for (int k = 0; k < RR; k++) {
            int rp = rpos[b * RR + k];
            rel[k] = usage[(size_t)b * MROWS + rp];
            minu = fminf(minu, rel[k]);
        }
        #pragma unroll
        for (int k = 0; k < RR; k++) {
            float ig = 1.f / (1.f + expf(-sif[2 * WC + k]));
            float I  = (rel[k] == minu) ? 1.f : 0.f;
            sww[k] = wg * (ig * read_w[b * RR + k] + (1.f - ig) * I);
        }
    }
    __syncthreads();

    for (int t = threadIdx.x; t < RR * WC; t += blockDim.x) {
        int k = t >> 6, w = t & 63;
        g_rows[b][k][w] = rvec[(b * RR + k) * WC + w] + sww[k] * swv[w];
    }
}

// ================= Kernel 2: streaming d2 scan + per-block top-8 =================
__global__ void __launch_bounds__(256, 4) k_scan(const float* __restrict__ mem,
                                                 const int* __restrict__ rpos) {
    const int b = blockIdx.y;
    const int row0 = blockIdx.x * CHUNK;
    const int row_end = row0 + CHUNK;
    const int lane = threadIdx.x & 31;
    const int warp = threadIdx.x >> 5;
    const int li = lane & 7;     // 8 lanes per row
    const int pg = lane >> 3;    // 4 rows per warp

    __shared__ int srp[RR];
    __shared__ float sd[256];
    __shared__ int   si[256];
    if (threadIdx.x < RR) srp[threadIdx.x] = rpos[b * RR + threadIdx.x];
    __syncthreads();

    bool has = false;
    #pragma unroll
    for (int k = 0; k < RR; k++) has |= (srp[k] >= row0 && srp[k] < row_end);

    // q slice for this lane
    float4 qa = *(const float4*)&g_q[b][li * 8];
    float4 qb = *(const float4*)&g_q[b][li * 8 + 4];

    float ld[8]; int lix[8];
    #pragma unroll
    for (int k = 0; k < 8; k++) { ld[k] = INFINITY; lix[k] = 0x7fffffff; }

    const float* base = mem + (size_t)b * MROWS * WC;
    const int iters = (CHUNK + 31) / 32;

    for (int it = 0; it < iters; ++it) {
        int row = row0 + it * 32 + warp * 4 + pg;
        int rowc = min(row, MROWS - 1);
        const float4* p = (const float4*)(base + (size_t)rowc * WC + li * 8);
        float4 v0, v1;
        if (!has) {
            v0 = __ldcs(p);
            v1 = __ldcs(p + 1);
        } else {
            int src = -1;
            #pragma unroll
            for (int k = RR - 1; k >= 0; --k)
                if (src < 0 && srp[k] == rowc) src = k;   // last write wins
            if (src >= 0) {
                const float4* gp = (const float4*)&g_rows[b][src][li * 8];
                v0 = gp[0]; v1 = gp[1];
            } else {
                v0 = __ldcs(p); v1 = __ldcs(p + 1);
            }
        }
        float dx;
        float acc;
        dx = v0.x - qa.x; acc  = dx * dx;
        dx = v0.y - qa.y; acc += dx * dx;
        dx = v0.z - qa.z; acc += dx * dx;
        dx = v0.w - qa.w; acc += dx * dx;
        dx = v1.x - qb.x; acc += dx * dx;
        dx = v1.y - qb.y; acc += dx * dx;
        dx = v1.z - qb.z; acc += dx * dx;
        dx = v1.w - qb.w; acc += dx * dx;
        // reduce across the 8 lanes of this row
        acc += __shfl_xor_sync(0xffffffffu, acc, 1);
        acc += __shfl_xor_sync(0xffffffffu, acc, 2);
        acc += __shfl_xor_sync(0xffffffffu, acc, 4);

        if (li == 0 && row < row_end) {
            if (lt_pair(acc, row, ld[7], lix[7])) {
                float cv = acc; int ci = row;
                #pragma unroll
                for (int k = 0; k < 8; k++) {
                    bool sw = lt_pair(cv, ci, ld[k], lix[k]);
                    float td = ld[k]; int ti = lix[k];
                    if (sw) { ld[k] = cv; lix[k] = ci; cv = td; ci = ti; }
                }
            }
        }
    }

    // block merge: 32 producers (li==0) dump their sorted-8 to shared
    if (li == 0) {
        int slot = threadIdx.x >> 3;   // 0..31
        #pragma unroll
        for (int k = 0; k < 8; k++) { sd[slot * 8 + k] = ld[k]; si[slot * 8 + k] = lix[k]; }
    }
    __syncthreads();

    if (threadIdx.x < 32) {
        int l = threadIdx.x;
        for (int s = 0; s < 8; s++) {
            float bd = INFINITY; int bi = 0x7fffffff; int bs = -1;
            for (int k = l; k < 256; k += 32)
                if (lt_pair(sd[k], si[k], bd, bi)) { bd = sd[k]; bi = si[k]; bs = k; }
            #pragma unroll
            for (int off = 16; off; off >>= 1) {
                float od = __shfl_xor_sync(0xffffffffu, bd, off);
                int   oi = __shfl_xor_sync(0xffffffffu, bi, off);
                int   os = __shfl_xor_sync(0xffffffffu, bs, off);
                if (lt_pair(od, oi, bd, bi)) { bd = od; bi = oi; bs = os; }
            }
            if (l == 0) {
                g_cand_d[b][blockIdx.x * 8 + s] = bd;
                g_cand_i[b][blockIdx.x * 8 + s] = bi;
                if (bs >= 0) sd[bs] = INFINITY;
            }
            __syncwarp();
        }
    }
}

// ================= Kernel 3: merge candidates, gather output =================
__global__ void k_final(const float* __restrict__ mem, const int* __restrict__ rpos,
                        float* __restrict__ out) {
    int b = blockIdx.x;
    __shared__ float sd[NCAND];
    __shared__ int   si[NCAND];
    __shared__ int   srp[RR];
    __shared__ int   sel[8];

    for (int t = threadIdx.x; t < NCAND; t += blockDim.x) {
        sd[t] = g_cand_d[b][t];
        si[t] = g_cand_i[b][t];
    }
    if (threadIdx.x < RR) srp[threadIdx.x] = rpos[b * RR + threadIdx.x];
    __syncthreads();

    if (threadIdx.x < 32) {
        int l = threadIdx.x;
        for (int s = 0; s < 8; s++) {
            float bd = INFINITY; int bi = 0x7fffffff; int bs = -1;
            for (int k = l; k < NCAND; k += 32)
                if (lt_pair(sd[k], si[k], bd, bi)) { bd = sd[k]; bi = si[k]; bs = k; }
            #pragma unroll
            for (int off = 16; off; off >>= 1) {
                float od = __shfl_xor_sync(0xffffffffu, bd, off);
                int   oi = __shfl_xor_sync(0xffffffffu, bi, off);
                int   os = __shfl_xor_sync(0xffffffffu, bs, off);
                if (lt_pair(od, oi, bd, bi)) { bd = od; bi = oi; bs = os; }
            }
            if (l == 0) { sel[s] = bi; if (bs >= 0) sd[bs] = INFINITY; }
            __syncwarp();
        }
    }
    __syncthreads();

    for (int t = threadIdx.x; t < 8 * WC; t += blockDim.x) {
        int k = t >> 6, w = t & 63;
        int idx = sel[k];
        int src = -1;
        #pragma unroll
        for (int j = RR - 1; j >= 0; --j)
            if (src < 0 && srp[j] == idx) src = j;  // last write wins
        float v = (src >= 0) ? g_rows[b][src][w]
                             : mem[((size_t)b * MROWS + idx) * WC + w];
        out[(b * 8 + k) * WC + w] = v;
    }
}

// ================= launcher =================
extern "C" void kernel_launch(void* const* d_in, const int* in_sizes, int n_in,
                              void* d_out, int out_size) {
    const float* xi     = (const float*)d_in[0];
    const float* Wm     = (const float*)d_in[1];
    const float* b_lin  = (const float*)d_in[2];
    const float* mem    = (const float*)d_in[3];
    const float* usage  = (const float*)d_in[4];
    const float* read_w = (const float*)d_in[5];
    // d_in[6] write_weights: dead w.r.t. output
    const float* rvec   = (const float*)d_in[7];
    // d_in[8] last_used_mem: dead (only feeds rv[:,8,:] which is sliced off)
    const int*   rpos   = (const int*)d_in[9];
    // d_in[10] timestep: dead (only feeds usage update -> rw, never returned)
    float* out = (float*)d_out;

    k_iface<<<NB, 160>>>(xi, Wm, b_lin, usage, read_w, rvec, rpos);
    k_scan<<<dim3(NBLK, NB), 256>>>(mem, rpos);
    k_final<<<NB, 256>>>(mem, rpos, out);
}

// round 3
// speedup vs baseline: 1.2755x; 1.2755x over previous
#include <cuda_runtime.h>
#include <math.h>
#include <float.h>

#define NB    32
#define MROWS 100000
#define WC    64
#define RR    9
#define NIF   138
#define DIN   512
#define NBLK  18           // scan blocks per batch: 18*32=576 = 148 SMs * 4 resident (1 wave)
#define CHUNK 5556         // ceil(100000/18); NBLK*CHUNK >= MROWS
#define NCAND (NBLK*8)     // 144 candidates per batch
#define NSL   7            // d-dimension slices in iface GEMM

// -------- scratch (no allocation allowed) --------
__device__ float g_q[NB][WC];            // read_query
__device__ float g_rows[NB][RR][WC];     // updated memory rows at rp
__device__ float g_cand_d[NB][NCAND];
__device__ int   g_cand_i[NB][NCAND];

__device__ __forceinline__ bool lt_pair(float d1, int i1, float d2, int i2) {
    return d1 < d2 || (d1 == d2 && i1 < i2);
}

__device__ __forceinline__ float dist8(float4 v0, float4 v1, float4 qa, float4 qb) {
    float dx, acc;
    dx = v0.x - qa.x; acc  = dx * dx;
    dx = v0.y - qa.y; acc += dx * dx;
    dx = v0.z - qa.z; acc += dx * dx;
    dx = v0.w - qa.w; acc += dx * dx;
    dx = v1.x - qb.x; acc += dx * dx;
    dx = v1.y - qb.y; acc += dx * dx;
    dx = v1.z - qb.z; acc += dx * dx;
    dx = v1.w - qb.w; acc += dx * dx;
    return acc;
}

__device__ __forceinline__ void insert8(float cv, int ci, float (&ld)[8], int (&lix)[8]) {
    if (lt_pair(cv, ci, ld[7], lix[7])) {
        #pragma unroll
        for (int k = 0; k < 8; k++) {
            bool sw = lt_pair(cv, ci, ld[k], lix[k]);
            float td = ld[k]; int ti = lix[k];
            if (sw) { ld[k] = cv; lix[k] = ci; cv = td; ci = ti; }
        }
    }
}

// ================= Kernel 1: iface + derived small state =================
// 992 threads: 7 d-slices x 138 outputs, shared-mem partial reduction.
__global__ void k_iface(const float* __restrict__ xi, const float* __restrict__ Wm,
                        const float* __restrict__ b_lin, const float* __restrict__ usage,
                        const float* __restrict__ read_w, const float* __restrict__ rvec,
                        const int* __restrict__ rpos) {
    int b = blockIdx.x;
    __shared__ float sx[DIN];
    __shared__ float part[NSL][NIF];
    __shared__ float sif[NIF];
    __shared__ float sww[RR];
    __shared__ float swv[WC];

    int tid = threadIdx.x;
    for (int i = tid; i < DIN; i += blockDim.x) sx[i] = xi[b * DIN + i];
    __syncthreads();

    int s = tid / NIF;
    int j = tid - s * NIF;
    if (s < NSL) {
        int d0 = s * 74;
        int d1 = min(DIN, d0 + 74);
        float acc = 0.f;
        #pragma unroll 8
        for (int d = d0; d < d1; ++d) acc = fmaf(sx[d], Wm[d * NIF + j], acc);
        part[s][j] = acc;
    }
    __syncthreads();

    if (tid < NIF) {
        float acc = b_lin[tid];
        #pragma unroll
        for (int k = 0; k < NSL; k++) acc += part[k][tid];
        sif[tid] = acc;
        if (tid < WC) g_q[b][tid] = acc;                 // read_query
        if (tid >= WC && tid < 2 * WC) swv[tid - WC] = acc;  // write_vector
    }
    __syncthreads();

    if (tid == 0) {
        float wg = 1.f / (1.f + expf(-sif[NIF - 1]));
        float rel[RR];
        float minu = INFINITY;
        #pragma unroll
        for (int k = 0; k < RR; k++) {
            int rp = rpos[b * RR + k];
            rel[k] = usage[(size_t)b * MROWS + rp];
            minu = fminf(minu, rel[k]);
        }
        #pragma unroll
        for (int k = 0; k < RR; k++) {
            float ig = 1.f / (1.f + expf(-sif[2 * WC + k]));
            float I  = (rel[k] == minu) ? 1.f : 0.f;
            sww[k] = wg * (ig * read_w[b * RR + k] + (1.f - ig) * I);
        }
    }
    __syncthreads();

    for (int t = tid; t < RR * WC; t += blockDim.x) {
        int k = t >> 6, w = t & 63;
        g_rows[b][k][w] = rvec[(b * RR + k) * WC + w] + sww[k] * swv[w];
    }
}

// ================= Kernel 2: streaming d2 scan + per-block top-8 =================
__global__ void __launch_bounds__(256, 4) k_scan(const float* __restrict__ mem,
                                                 const int* __restrict__ rpos) {
    const int b = blockIdx.y;
    const int row0 = blockIdx.x * CHUNK;
    const int row_end = min(row0 + CHUNK, MROWS);
    const int lane = threadIdx.x & 31;
    const int warp = threadIdx.x >> 5;
    const int li = lane & 7;     // 8 lanes per row
    const int pg = lane >> 3;    // 4 rows per warp
    const unsigned gmask = 0xFFu << (pg * 8);

    __shared__ int srp[RR];
    __shared__ float sd[256];
    __shared__ int   si[256];
    if (threadIdx.x < RR) srp[threadIdx.x] = rpos[b * RR + threadIdx.x];
    __syncthreads();

    bool has = false;
    #pragma unroll
    for (int k = 0; k < RR; k++) has |= (srp[k] >= row0 && srp[k] < row_end);

    float4 qa = *(const float4*)&g_q[b][li * 8];
    float4 qb = *(const float4*)&g_q[b][li * 8 + 4];

    float ld[8]; int lix[8];
    #pragma unroll
    for (int k = 0; k < 8; k++) { ld[k] = INFINITY; lix[k] = 0x7fffffff; }

    const float* base = mem + (size_t)b * MROWS * WC;
    int r = row0 + warp * 4 + pg;
    const float* pA = base + (size_t)r * WC + li * 8;

    if (!has) {
        // ---- fast path: unroll-by-2 pipeline, 4 float4 loads in flight ----
        int nfull2 = (row_end - row0) >> 6;   // full 64-row double iterations
        for (int it = 0; it < nfull2; ++it) {
            float4 a0 = __ldcs((const float4*)pA);
            float4 a1 = __ldcs((const float4*)(pA + 4));
            float4 c0 = __ldcs((const float4*)(pA + 32 * WC));
            float4 c1 = __ldcs((const float4*)(pA + 32 * WC + 4));
            float accA = dist8(a0, a1, qa, qb);
            float accB = dist8(c0, c1, qa, qb);
            accA += __shfl_xor_sync(0xffffffffu, accA, 1);
            accA += __shfl_xor_sync(0xffffffffu, accA, 2);
            accA += __shfl_xor_sync(0xffffffffu, accA, 4);
            accB += __shfl_xor_sync(0xffffffffu, accB, 1);
            accB += __shfl_xor_sync(0xffffffffu, accB, 2);
            accB += __shfl_xor_sync(0xffffffffu, accB, 4);
            if (li == 0) {
                insert8(accA, r, ld, lix);
                insert8(accB, r + 32, ld, lix);
            }
            r += 64; pA += 64 * WC;
        }
        // remainder: up to 63 rows -> 2 guarded single iterations
        #pragma unroll
        for (int t = 0; t < 2; ++t) {
            if (r < row_end) {
                float4 a0 = __ldcs((const float4*)pA);
                float4 a1 = __ldcs((const float4*)(pA + 4));
                float acc = dist8(a0, a1, qa, qb);
                acc += __shfl_xor_sync(gmask, acc, 1);
                acc += __shfl_xor_sync(gmask, acc, 2);
                acc += __shfl_xor_sync(gmask, acc, 4);
                if (li == 0) insert8(acc, r, ld, lix);
            }
            r += 32; pA += 32 * WC;
        }
    } else {
        // ---- slow path (<= 9 of 576 blocks): per-row rp substitution ----
        int iters = (row_end - row0 + 31) >> 5;
        for (int it = 0; it < iters; ++it) {
            if (r < row_end) {
                int src = -1;
                #pragma unroll
                for (int k = RR - 1; k >= 0; --k)
                    if (src < 0 && srp[k] == r) src = k;   // last write wins
                float4 v0, v1;
                if (src >= 0) {
                    const float4* gp = (const float4*)&g_rows[b][src][li * 8];
                    v0 = gp[0]; v1 = gp[1];
                } else {
                    v0 = __ldcs((const float4*)pA);
                    v1 = __ldcs((const float4*)(pA + 4));
                }
                float acc = dist8(v0, v1, qa, qb);
                acc += __shfl_xor_sync(gmask, acc, 1);
                acc += __shfl_xor_sync(gmask, acc, 2);
                acc += __shfl_xor_sync(gmask, acc, 4);
                if (li == 0) insert8(acc, r, ld, lix);
            }
            r += 32; pA += 32 * WC;
        }
    }

    // block merge: 32 producers (li==0) dump their sorted-8 to shared
    if (li == 0) {
        int slot = threadIdx.x >> 3;   // 0..31
        #pragma unroll
        for (int k = 0; k < 8; k++) { sd[slot * 8 + k] = ld[k]; si[slot * 8 + k] = lix[k]; }
    }
    __syncthreads();

    if (threadIdx.x < 32) {
        int l = threadIdx.x;
        for (int s = 0; s < 8; s++) {
            float bd = INFINITY; int bi = 0x7fffffff; int bs = -1;
            for (int k = l; k < 256; k += 32)
                if (lt_pair(sd[k], si[k], bd, bi)) { bd = sd[k]; bi = si[k]; bs = k; }
            #pragma unroll
            for (int off = 16; off; off >>= 1) {
                float od = __shfl_xor_sync(0xffffffffu, bd, off);
                int   oi = __shfl_xor_sync(0xffffffffu, bi, off);
                int   os = __shfl_xor_sync(0xffffffffu, bs, off);
                if (lt_pair(od, oi, bd, bi)) { bd = od; bi = oi; bs = os; }
            }
            if (l == 0) {
                g_cand_d[b][blockIdx.x * 8 + s] = bd;
                g_cand_i[b][blockIdx.x * 8 + s] = bi;
                if (bs >= 0) sd[bs] = INFINITY;
            }
            __syncwarp();
        }
    }
}

// ================= Kernel 3: merge candidates, gather output =================
__global__ void k_final(const float* __restrict__ mem, const int* __restrict__ rpos,
                        float* __restrict__ out) {
    int b = blockIdx.x;
    __shared__ float sd[NCAND];
    __shared__ int   si[NCAND];
    __shared__ int   srp[RR];
    __shared__ int   sel[8];

    for (int t = threadIdx.x; t < NCAND; t += blockDim.x) {
        sd[t] = g_cand_d[b][t];
        si[t] = g_cand_i[b][t];
    }
    if (threadIdx.x < RR) srp[threadIdx.x] = rpos[b * RR + threadIdx.x];
    __syncthreads();

    if (threadIdx.x < 32) {
        int l = threadIdx.x;
        for (int s = 0; s < 8; s++) {
            float bd = INFINITY; int bi = 0x7fffffff; int bs = -1;
            for (int k = l; k < NCAND; k += 32)
                if (lt_pair(sd[k], si[k], bd, bi)) { bd = sd[k]; bi = si[k]; bs = k; }
            #pragma unroll
            for (int off = 16; off; off >>= 1) {
                float od = __shfl_xor_sync(0xffffffffu, bd, off);
                int   oi = __shfl_xor_sync(0xffffffffu, bi, off);
                int   os = __shfl_xor_sync(0xffffffffu, bs, off);
                if (lt_pair(od, oi, bd, bi)) { bd = od; bi = oi; bs = os; }
            }
            if (l == 0) { sel[s] = bi; if (bs >= 0) sd[bs] = INFINITY; }
            __syncwarp();
        }
    }
    __syncthreads();

    for (int t = threadIdx.x; t < 8 * WC; t += blockDim.x) {
        int k = t >> 6, w = t & 63;
        int idx = sel[k];
        int src = -1;
        #pragma unroll
        for (int j = RR - 1; j >= 0; --j)
            if (src < 0 && srp[j] == idx) src = j;  // last write wins
        float v = (src >= 0) ? g_rows[b][src][w]
                             : mem[((size_t)b * MROWS + idx) * WC + w];
        out[(b * 8 + k) * WC + w] = v;
    }
}

// ================= launcher =================
extern "C" void kernel_launch(void* const* d_in, const int* in_sizes, int n_in,
                              void* d_out, int out_size) {
    const float* xi     = (const float*)d_in[0];
    const float* Wm     = (const float*)d_in[1];
    const float* b_lin  = (const float*)d_in[2];
    const float* mem    = (const float*)d_in[3];
    const float* usage  = (const float*)d_in[4];
    const float* read_w = (const float*)d_in[5];
    // d_in[6] write_weights: dead w.r.t. output
    const float* rvec   = (const float*)d_in[7];
    // d_in[8] last_used_mem: dead (only feeds rv[:,8,:] which is sliced off)
    const int*   rpos   = (const int*)d_in[9];
    // d_in[10] timestep: dead (only feeds usage update -> rw, never returned)
    float* out = (float*)d_out;

    k_iface<<<NB, 992>>>(xi, Wm, b_lin, usage, read_w, rvec, rpos);
    k_scan<<<dim3(NBLK, NB), 256>>>(mem, rpos);
    k_final<<<NB, 256>>>(mem, rpos, out);
}

// round 4
// speedup vs baseline: 1.5465x; 1.2125x over previous
#include <cuda_runtime.h>
#include <math.h>
#include <float.h>

#define NB    32
#define MROWS 100000
#define WC    64
#define RR    9
#define NIF   138
#define DIN   512
#define NBLK  37           // 37*32 = 1184 blocks = 8 per SM (2 waves at 4-resident)
#define CHUNK 2703         // ceil(100000/37)
#define NCAND (NBLK*8)     // 296 candidates per batch
#define NPOOL (256 + RR)   // block merge pool: 32 producers x 8 + 9 patch rows
#define NPART 4            // d-partition blocks per batch in iface GEMM

// -------- scratch (no allocation allowed) --------
__device__ float g_part[NB][NPART][NIF];
__device__ float g_q[NB][WC];            // read_query
__device__ float g_rows[NB][RR][WC];     // updated memory rows at rp
__device__ float g_cand_d[NB][NCAND];
__device__ int   g_cand_i[NB][NCAND];

__device__ __forceinline__ bool lt_pair(float d1, int i1, float d2, int i2) {
    return d1 < d2 || (d1 == d2 && i1 < i2);
}

__device__ __forceinline__ float dist8(float4 v0, float4 v1, float4 qa, float4 qb) {
    float dx, acc;
    dx = v0.x - qa.x; acc  = dx * dx;
    dx = v0.y - qa.y; acc += dx * dx;
    dx = v0.z - qa.z; acc += dx * dx;
    dx = v0.w - qa.w; acc += dx * dx;
    dx = v1.x - qb.x; acc += dx * dx;
    dx = v1.y - qb.y; acc += dx * dx;
    dx = v1.z - qb.z; acc += dx * dx;
    dx = v1.w - qb.w; acc += dx * dx;
    return acc;
}

// insert with stale-row exclusion; the 9-compare only runs on the rare
// "beats current 8th best" path.
__device__ __forceinline__ void insert8x(float cv, int ci, float (&ld)[8], int (&lix)[8],
                                         const int* __restrict__ srp) {
    if (lt_pair(cv, ci, ld[7], lix[7])) {
        bool stale = false;
        #pragma unroll
        for (int k = 0; k < RR; k++) stale |= (srp[k] == ci);
        if (!stale) {
            #pragma unroll
            for (int k = 0; k < 8; k++) {
                bool sw = lt_pair(cv, ci, ld[k], lix[k]);
                float td = ld[k]; int ti = lix[k];
                if (sw) { ld[k] = cv; lix[k] = ci; cv = td; ci = ti; }
            }
        }
    }
}

// ================= Kernel 1a: iface GEMM partials =================
// grid (NPART, NB), 552 threads: 4 d-subslices x 138 outputs per block.
__global__ void k_part(const float* __restrict__ xi, const float* __restrict__ Wm) {
    int b = blockIdx.y;
    int dbase = blockIdx.x * (DIN / NPART);   // 128-wide d slice
    __shared__ float sx[DIN / NPART];
    __shared__ float pp[4][NIF];

    int tid = threadIdx.x;
    if (tid < DIN / NPART) sx[tid] = xi[b * DIN + dbase + tid];
    __syncthreads();

    int s = tid / NIF;
    int j = tid - s * NIF;
    if (s < 4) {
        int d0 = dbase + s * 32;
        float acc = 0.f;
        #pragma unroll
        for (int d = 0; d < 32; d++)
            acc = fmaf(sx[s * 32 + d], Wm[(d0 + d) * NIF + j], acc);
        pp[s][j] = acc;
    }
    __syncthreads();

    if (tid < NIF)
        g_part[b][blockIdx.x][tid] = pp[0][tid] + pp[1][tid] + pp[2][tid] + pp[3][tid];
}

// ================= Kernel 1b: finish iface, build q / updated rows =================
__global__ void k_ifin(const float* __restrict__ b_lin, const float* __restrict__ usage,
                       const float* __restrict__ read_w, const float* __restrict__ rvec,
                       const int* __restrict__ rpos) {
    int b = blockIdx.x;
    __shared__ float sif[NIF];
    __shared__ float sww[RR];
    __shared__ float swv[WC];
    int tid = threadIdx.x;

    if (tid < NIF) {
        float acc = b_lin[tid];
        #pragma unroll
        for (int p = 0; p < NPART; p++) acc += g_part[b][p][tid];
        sif[tid] = acc;
        if (tid < WC) g_q[b][tid] = acc;                    // read_query
        if (tid >= WC && tid < 2 * WC) swv[tid - WC] = acc; // write_vector
    }
    __syncthreads();

    if (tid == 0) {
        float wg = 1.f / (1.f + expf(-sif[NIF - 1]));
        float rel[RR];
        float minu = INFINITY;
        #pragma unroll
        for (int k = 0; k < RR; k++) {
            int rp = rpos[b * RR + k];
            rel[k] = usage[(size_t)b * MROWS + rp];
            minu = fminf(minu, rel[k]);
        }
        #pragma unroll
        for (int k = 0; k < RR; k++) {
            float ig = 1.f / (1.f + expf(-sif[2 * WC + k]));
            float I  = (rel[k] == minu) ? 1.f : 0.f;
            sww[k] = wg * (ig * read_w[b * RR + k] + (1.f - ig) * I);
        }
    }
    __syncthreads();

    for (int t = tid; t < RR * WC; t += blockDim.x) {
        int k = t >> 6, w = t & 63;
        g_rows[b][k][w] = rvec[(b * RR + k) * WC + w] + sww[k] * swv[w];
    }
}

// ================= Kernel 2: streaming d2 scan + per-block top-8 =================
// Single fast path for ALL blocks; rp rows excluded at insert time, updated
// rows appended to the merge pool post-loop.
__global__ void __launch_bounds__(256, 4) k_scan(const float* __restrict__ mem,
                                                 const int* __restrict__ rpos) {
    const int b = blockIdx.y;
    const int row0 = blockIdx.x * CHUNK;
    const int row_end = min(row0 + CHUNK, MROWS);
    const int lane = threadIdx.x & 31;
    const int warp = threadIdx.x >> 5;
    const int li = lane & 7;     // 8 lanes per row
    const int pg = lane >> 3;    // 4 rows per warp
    const unsigned gmask = 0xFFu << (pg * 8);

    __shared__ int srp[RR];
    __shared__ float sd[NPOOL];
    __shared__ int   si[NPOOL];
    if (threadIdx.x < RR) srp[threadIdx.x] = rpos[b * RR + threadIdx.x];
    __syncthreads();

    float4 qa = *(const float4*)&g_q[b][li * 8];
    float4 qb = *(const float4*)&g_q[b][li * 8 + 4];

    float ld[8]; int lix[8];
    #pragma unroll
    for (int k = 0; k < 8; k++) { ld[k] = INFINITY; lix[k] = 0x7fffffff; }

    const float* base = mem + (size_t)b * MROWS * WC;
    int r = row0 + warp * 4 + pg;
    const float* pA = base + (size_t)r * WC + li * 8;

    // unroll-by-2 pipeline: 4 float4 loads in flight per thread
    int nfull2 = (row_end - row0) >> 6;
    for (int it = 0; it < nfull2; ++it) {
        float4 a0 = __ldcs((const float4*)pA);
        float4 a1 = __ldcs((const float4*)(pA + 4));
        float4 c0 = __ldcs((const float4*)(pA + 32 * WC));
        float4 c1 = __ldcs((const float4*)(pA + 32 * WC + 4));
        float accA = dist8(a0, a1, qa, qb);
        float accB = dist8(c0, c1, qa, qb);
        accA += __shfl_xor_sync(0xffffffffu, accA, 1);
        accA += __shfl_xor_sync(0xffffffffu, accA, 2);
        accA += __shfl_xor_sync(0xffffffffu, accA, 4);
        accB += __shfl_xor_sync(0xffffffffu, accB, 1);
        accB += __shfl_xor_sync(0xffffffffu, accB, 2);
        accB += __shfl_xor_sync(0xffffffffu, accB, 4);
        if (li == 0) {
            insert8x(accA, r, ld, lix, srp);
            insert8x(accB, r + 32, ld, lix, srp);
        }
        r += 64; pA += 64 * WC;
    }
    // remainder: up to 63 rows -> 2 guarded single iterations (uniform per row-group)
    #pragma unroll
    for (int t = 0; t < 2; ++t) {
        if (r < row_end) {
            float4 a0 = __ldcs((const float4*)pA);
            float4 a1 = __ldcs((const float4*)(pA + 4));
            float acc = dist8(a0, a1, qa, qb);
            acc += __shfl_xor_sync(gmask, acc, 1);
            acc += __shfl_xor_sync(gmask, acc, 2);
            acc += __shfl_xor_sync(gmask, acc, 4);
            if (li == 0) insert8x(acc, r, ld, lix, srp);
        }
        r += 32; pA += 32 * WC;
    }

    // producers dump sorted-8 to pool slots [0,256)
    if (li == 0) {
        int slot = threadIdx.x >> 3;
        #pragma unroll
        for (int k = 0; k < 8; k++) { sd[slot * 8 + k] = ld[k]; si[slot * 8 + k] = lix[k]; }
    }

    // warp 0: patch candidates for rp rows in this block's range (slots [256,265))
    if (warp == 0) {
        #pragma unroll
        for (int k = 0; k < RR; k++) {
            int rr = srp[k];
            bool use = (rr >= row0 && rr < row_end);
            #pragma unroll
            for (int k2 = k + 1; k2 < RR; k2++) use &= (srp[k2] != rr);  // last write wins
            float accv = 0.f;
            if (lane < 8) {
                float4 g0 = *(const float4*)&g_rows[b][k][lane * 8];
                float4 g1 = *(const float4*)&g_rows[b][k][lane * 8 + 4];
                accv = dist8(g0, g1, qa, qb);
                accv += __shfl_xor_sync(0xFFu, accv, 1);
                accv += __shfl_xor_sync(0xFFu, accv, 2);
                accv += __shfl_xor_sync(0xFFu, accv, 4);
            }
            if (lane == 0) {
                sd[256 + k] = use ? accv : INFINITY;
                si[256 + k] = use ? rr   : 0x7fffffff;
            }
        }
    }
    __syncthreads();

    // merge pool (265 entries) -> block top-8
    if (threadIdx.x < 32) {
        int l = threadIdx.x;
        for (int s = 0; s < 8; s++) {
            float bd = INFINITY; int bi = 0x7fffffff; int bs = -1;
            for (int k = l; k < NPOOL; k += 32)
                if (lt_pair(sd[k], si[k], bd, bi)) { bd = sd[k]; bi = si[k]; bs = k; }
            #pragma unroll
            for (int off = 16; off; off >>= 1) {
                float od = __shfl_xor_sync(0xffffffffu, bd, off);
                int   oi = __shfl_xor_sync(0xffffffffu, bi, off);
                int   os = __shfl_xor_sync(0xffffffffu, bs, off);
                if (lt_pair(od, oi, bd, bi)) { bd = od; bi = oi; bs = os; }
            }
            if (l == 0) {
                g_cand_d[b][blockIdx.x * 8 + s] = bd;
                g_cand_i[b][blockIdx.x * 8 + s] = bi;
                if (bs >= 0) sd[bs] = INFINITY;
            }
            __syncwarp();
        }
    }
}

// ================= Kernel 3: merge candidates, gather output =================
__global__ void k_final(const float* __restrict__ mem, const int* __restrict__ rpos,
                        float* __restrict__ out) {
    int b = blockIdx.x;
    __shared__ float sd[NCAND];
    __shared__ int   si[NCAND];
    __shared__ int   srp[RR];
    __shared__ int   sel[8];

    for (int t = threadIdx.x; t < NCAND; t += blockDim.x) {
        sd[t] = g_cand_d[b][t];
        si[t] = g_cand_i[b][t];
    }
    if (threadIdx.x < RR) srp[threadIdx.x] = rpos[b * RR + threadIdx.x];
    __syncthreads();

    if (threadIdx.x < 32) {
        int l = threadIdx.x;
        for (int s = 0; s < 8; s++) {
            float bd = INFINITY; int bi = 0x7fffffff; int bs = -1;
            for (int k = l; k < NCAND; k += 32)
                if (lt_pair(sd[k], si[k], bd, bi)) { bd = sd[k]; bi = si[k]; bs = k; }
            #pragma unroll
            for (int off = 16; off; off >>= 1) {
                float od = __shfl_xor_sync(0xffffffffu, bd, off);
                int   oi = __shfl_xor_sync(0xffffffffu, bi, off);
                int   os = __shfl_xor_sync(0xffffffffu, bs, off);
                if (lt_pair(od, oi, bd, bi)) { bd = od; bi = oi; bs = os; }
            }
            if (l == 0) { sel[s] = bi; if (bs >= 0) sd[bs] = INFINITY; }
            __syncwarp();
        }
    }
    __syncthreads();

    for (int t = threadIdx.x; t < 8 * WC; t += blockDim.x) {
        int k = t >> 6, w = t & 63;
        int idx = sel[k];
        int src = -1;
        #pragma unroll
        for (int j = RR - 1; j >= 0; --j)
            if (src < 0 && srp[j] == idx) src = j;  // last write wins
        float v = (src >= 0) ? g_rows[b][src][w]
                             : mem[((size_t)b * MROWS + idx) * WC + w];
        out[(b * 8 + k) * WC + w] = v;
    }
}

// ================= launcher =================
extern "C" void kernel_launch(void* const* d_in, const int* in_sizes, int n_in,
                              void* d_out, int out_size) {
    const float* xi     = (const float*)d_in[0];
    const float* Wm     = (const float*)d_in[1];
    const float* b_lin  = (const float*)d_in[2];
    const float* mem    = (const float*)d_in[3];
    const float* usage  = (const float*)d_in[4];
    const float* read_w = (const float*)d_in[5];
    // d_in[6] write_weights: dead w.r.t. output
    const float* rvec   = (const float*)d_in[7];
    // d_in[8] last_used_mem: dead (only feeds rv[:,8,:] which is sliced off)
    const int*   rpos   = (const int*)d_in[9];
    // d_in[10] timestep: dead (only feeds usage update -> rw, never returned)
    float* out = (float*)d_out;

    k_part<<<dim3(NPART, NB), 552>>>(xi, Wm);
    k_ifin<<<NB, 160>>>(b_lin, usage, read_w, rvec, rpos);
    k_scan<<<dim3(NBLK, NB), 256>>>(mem, rpos);
    k_final<<<NB, 256>>>(mem, rpos, out);
}